// round 5
// baseline (speedup 1.0000x reference)
#include <cuda_runtime.h>
#include <cstdint>
#include <math.h>

// Problem dims
namespace {
constexpr int T_ = 2048;          // tokens = S*B
constexpr int H_ = 1024;
constexpr int F_ = 4096;
constexpr int E_ = 4;
constexpr int K2_ = E_ * F_;      // 16384 (fc2 reduction dim)

// Tiling
constexpr int BM = 128, BN = 128, BK = 32;
constexpr int ASTR = BK + 4;      // 36 : conflict-free A fragment LDS
constexpr int BSTR = BN + 8;      // 136: conflict-free B fragment LDS
constexpr int ASZ = BM * ASTR;    // floats per A buffer
constexpr int BSZ = BK * BSTR;    // floats per B buffer
constexpr int SMEM_BYTES = (2 * ASZ + 2 * BSZ) * 4;   // 71680 B
}

// Scratch: A'[t, e*F + f] = p[t,e] * gelu(X @ W1_e)   (fp32, 128 MiB)
__device__ float g_act[(size_t)T_ * K2_];

__device__ __forceinline__ float to_tf32(float x) {
    unsigned r;
    asm("cvt.rna.tf32.f32 %0, %1;" : "=r"(r) : "f"(x));
    return __uint_as_float(r);
}

__device__ __forceinline__ void mma8(float* c, const unsigned* a, const unsigned* b) {
    asm volatile(
        "mma.sync.aligned.m16n8k8.row.col.f32.tf32.tf32.f32 "
        "{%0,%1,%2,%3}, {%4,%5,%6,%7}, {%8,%9}, {%0,%1,%2,%3};"
        : "+f"(c[0]), "+f"(c[1]), "+f"(c[2]), "+f"(c[3])
        : "r"(a[0]), "r"(a[1]), "r"(a[2]), "r"(a[3]), "r"(b[0]), "r"(b[1]));
}

__device__ __forceinline__ float gelu_exact(float x) {
    return 0.5f * x * (1.0f + erff(x * 0.70710678118654752f));
}

// Shared mainloop: C[128,128] += A[128, kTiles*32] (row-major, lda)
//                           @ B[kTiles*32, 128]   (row-major, ldb)
// Ag points at &A[m_base][0]; Bg points at &B[0][n_base].
__device__ __forceinline__ void gemm_tiles(
    const float* __restrict__ Ag, size_t lda,
    const float* __restrict__ Bg, size_t ldb,
    int kTiles, float c[4][4][4])
{
    extern __shared__ float sm[];
    float* As = sm;                 // [2][BM][ASTR]
    float* Bs = sm + 2 * ASZ;       // [2][BK][BSTR]
    const int tid  = threadIdx.x;
    const int lane = tid & 31;
    const int wm = ((tid >> 5) >> 2) * 64;   // warp M offset (2 warps in M)
    const int wn = ((tid >> 5) & 3) * 32;    // warp N offset (4 warps in N)
    // Global staging maps: A: 32 rows/pass x (8 thr * float4); B: 8 rows/pass x (32 thr * float4)
    const int ar = tid >> 3, ac = (tid & 7) * 4;
    const int bk = tid >> 5, bn = (tid & 31) * 4;

    float4 av[4], bv[4];
#pragma unroll
    for (int i = 0; i < 4; i++) {
        av[i] = *reinterpret_cast<const float4*>(Ag + (size_t)(ar + 32 * i) * lda + ac);
        bv[i] = *reinterpret_cast<const float4*>(Bg + (size_t)(bk + 8 * i) * ldb + bn);
    }
    auto stage = [&](int buf) {
        float* Ad = As + buf * ASZ;
        float* Bd = Bs + buf * BSZ;
#pragma unroll
        for (int i = 0; i < 4; i++) {
            float4 t;
            t.x = to_tf32(av[i].x); t.y = to_tf32(av[i].y);
            t.z = to_tf32(av[i].z); t.w = to_tf32(av[i].w);
            *reinterpret_cast<float4*>(Ad + (ar + 32 * i) * ASTR + ac) = t;
            float4 u;
            u.x = to_tf32(bv[i].x); u.y = to_tf32(bv[i].y);
            u.z = to_tf32(bv[i].z); u.w = to_tf32(bv[i].w);
            *reinterpret_cast<float4*>(Bd + (bk + 8 * i) * BSTR + bn) = u;
        }
    };
    stage(0);
    __syncthreads();

    for (int kt = 0; kt < kTiles; kt++) {
        if (kt + 1 < kTiles) {
            size_t ko = (size_t)(kt + 1) * BK;
#pragma unroll
            for (int i = 0; i < 4; i++) {
                av[i] = *reinterpret_cast<const float4*>(Ag + (size_t)(ar + 32 * i) * lda + ko + ac);
                bv[i] = *reinterpret_cast<const float4*>(Bg + (ko + (size_t)(bk + 8 * i)) * ldb + bn);
            }
        }
        const float* Ac = As + (kt & 1) * ASZ;
        const float* Bc = Bs + (kt & 1) * BSZ;
#pragma unroll
        for (int ks = 0; ks < 4; ks++) {
            unsigned af[4][4], bf[4][2];
            const int acol = ks * 8 + (lane & 3);
            const int arow = wm + (lane >> 2);
#pragma unroll
            for (int mi = 0; mi < 4; mi++) {
                int r = arow + mi * 16;
                af[mi][0] = __float_as_uint(Ac[r * ASTR + acol]);
                af[mi][1] = __float_as_uint(Ac[(r + 8) * ASTR + acol]);
                af[mi][2] = __float_as_uint(Ac[r * ASTR + acol + 4]);
                af[mi][3] = __float_as_uint(Ac[(r + 8) * ASTR + acol + 4]);
            }
            const int brow = ks * 8 + (lane & 3);
#pragma unroll
            for (int ni = 0; ni < 4; ni++) {
                int cc = wn + ni * 8 + (lane >> 2);
                bf[ni][0] = __float_as_uint(Bc[brow * BSTR + cc]);
                bf[ni][1] = __float_as_uint(Bc[(brow + 4) * BSTR + cc]);
            }
#pragma unroll
            for (int mi = 0; mi < 4; mi++)
#pragma unroll
                for (int ni = 0; ni < 4; ni++)
                    mma8(c[mi][ni], af[mi], bf[ni]);
        }
        if (kt + 1 < kTiles) {
            stage((kt + 1) & 1);
            __syncthreads();
        }
    }
}

// fc1: A'[t, e*F + n] = probs[t,e] * gelu( (X @ W1_e)[t,n] )
__global__ void __launch_bounds__(256, 1) fc1_kernel(
    const float* __restrict__ X, const float* __restrict__ W1,
    const float* __restrict__ probs)
{
    const int e = blockIdx.z;
    const int m_base = blockIdx.y * BM;
    const int n_base = blockIdx.x * BN;
    float c[4][4][4];
#pragma unroll
    for (int i = 0; i < 4; i++)
#pragma unroll
        for (int j = 0; j < 4; j++)
#pragma unroll
            for (int k = 0; k < 4; k++) c[i][j][k] = 0.f;

    const float* Ag = X + (size_t)m_base * H_;
    const float* Bg = W1 + (size_t)e * H_ * F_ + n_base;
    gemm_tiles(Ag, H_, Bg, F_, H_ / BK, c);

    const int lane = threadIdx.x & 31;
    const int wm = ((threadIdx.x >> 5) >> 2) * 64;
    const int wn = ((threadIdx.x >> 5) & 3) * 32;
#pragma unroll
    for (int mi = 0; mi < 4; mi++) {
        int r0 = m_base + wm + mi * 16 + (lane >> 2);
        int r1 = r0 + 8;
        float pa = probs[r0 * E_ + e];
        float pb = probs[r1 * E_ + e];
#pragma unroll
        for (int ni = 0; ni < 4; ni++) {
            int cc = n_base + wn + ni * 8 + (lane & 3) * 2;
            float2 v0 = make_float2(gelu_exact(c[mi][ni][0]) * pa,
                                    gelu_exact(c[mi][ni][1]) * pa);
            float2 v1 = make_float2(gelu_exact(c[mi][ni][2]) * pb,
                                    gelu_exact(c[mi][ni][3]) * pb);
            *reinterpret_cast<float2*>(&g_act[(size_t)r0 * K2_ + (size_t)e * F_ + cc]) = v0;
            *reinterpret_cast<float2*>(&g_act[(size_t)r1 * K2_ + (size_t)e * F_ + cc]) = v1;
        }
    }
}

// fc2: out[t,h] = A'[t, :] @ W2'[:, h] + residual[t,h]   (K = E*F = 16384)
__global__ void __launch_bounds__(256, 1) fc2_kernel(
    const float* __restrict__ W2, const float* __restrict__ resid,
    float* __restrict__ out)
{
    const int m_base = blockIdx.y * BM;
    const int n_base = blockIdx.x * BN;
    float c[4][4][4];
#pragma unroll
    for (int i = 0; i < 4; i++)
#pragma unroll
        for (int j = 0; j < 4; j++)
#pragma unroll
            for (int k = 0; k < 4; k++) c[i][j][k] = 0.f;

    const float* Ag = g_act + (size_t)m_base * K2_;
    const float* Bg = W2 + n_base;
    gemm_tiles(Ag, K2_, Bg, H_, K2_ / BK, c);

    const int lane = threadIdx.x & 31;
    const int wm = ((threadIdx.x >> 5) >> 2) * 64;
    const int wn = ((threadIdx.x >> 5) & 3) * 32;
#pragma unroll
    for (int mi = 0; mi < 4; mi++) {
        int r0 = m_base + wm + mi * 16 + (lane >> 2);
        int r1 = r0 + 8;
#pragma unroll
        for (int ni = 0; ni < 4; ni++) {
            int cc = n_base + wn + ni * 8 + (lane & 3) * 2;
            float2 rr0 = *reinterpret_cast<const float2*>(&resid[(size_t)r0 * H_ + cc]);
            float2 rr1 = *reinterpret_cast<const float2*>(&resid[(size_t)r1 * H_ + cc]);
            float2 v0 = make_float2(c[mi][ni][0] + rr0.x, c[mi][ni][1] + rr0.y);
            float2 v1 = make_float2(c[mi][ni][2] + rr1.x, c[mi][ni][3] + rr1.y);
            *reinterpret_cast<float2*>(&out[(size_t)r0 * H_ + cc]) = v0;
            *reinterpret_cast<float2*>(&out[(size_t)r1 * H_ + cc]) = v1;
        }
    }
}

extern "C" void kernel_launch(void* const* d_in, const int* in_sizes, int n_in,
                              void* d_out, int out_size) {
    (void)in_sizes; (void)n_in; (void)out_size;
    const float* x     = (const float*)d_in[0];   // hidden_states [S,B,H] == [T,H]
    const float* resid = (const float*)d_in[1];   // mlp_residual  [T,H]
    const float* probs = (const float*)d_in[2];   // [T,E] (already masked+renormalized)
    // d_in[3] routing_map: redundant (probs is zero off the top-k), ignored
    const float* w1    = (const float*)d_in[4];   // [E,H,F]
    const float* w2    = (const float*)d_in[5];   // [E,F,H] == [E*F, H]
    float* out = (float*)d_out;

    cudaFuncSetAttribute(fc1_kernel, cudaFuncAttributeMaxDynamicSharedMemorySize, SMEM_BYTES);
    cudaFuncSetAttribute(fc2_kernel, cudaFuncAttributeMaxDynamicSharedMemorySize, SMEM_BYTES);

    dim3 g1(F_ / BN, T_ / BM, E_);   // 32 x 16 x 4 = 2048 blocks
    fc1_kernel<<<g1, 256, SMEM_BYTES>>>(x, w1, probs);
    dim3 g2(H_ / BN, T_ / BM);       // 8 x 16 = 128 blocks
    fc2_kernel<<<g2, 256, SMEM_BYTES>>>(w2, resid, out);
}

// round 12
// speedup vs baseline: 2.2881x; 2.2881x over previous
#include <cuda_runtime.h>
#include <cstdint>
#include <math.h>

namespace {
constexpr int T_ = 2048;          // tokens = S*B
constexpr int H_ = 1024;
constexpr int F_ = 4096;
constexpr int E_ = 4;

// GEMM tiling: block 128(M) x 256(N) x 32(K), 8 warps as 2(M) x 4(N), warp 64x64
constexpr int BM = 128, BN = 256, BK = 32;
constexpr int STAGES = 4;
constexpr int ASTR = 36;                          // A smem row stride (floats)
constexpr int BSTR = 264;                         // B smem row stride (floats)
constexpr int A_BYTES = BM * ASTR * 4;            // 18432
constexpr int B_BYTES = BK * BSTR * 4;            // 33792
constexpr int STAGE_BYTES = A_BYTES + B_BYTES;    // 52224 (multiple of 16)
constexpr int HDR = 1024;                         // header: gathered index list
constexpr int SMEM_BYTES = HDR + STAGES * STAGE_BYTES;   // 209920 <= 227328
}

// Scratch (__device__ globals per allocation rules; zero-initialized by runtime)
__device__ float g_x  [(size_t)T_ * H_];          // tf32-rounded X            (8 MB)
__device__ float g_w1r[(size_t)E_ * H_ * F_];     // tf32-rounded W1           (64 MB)
__device__ float g_w2r[(size_t)E_ * F_ * H_];     // tf32-rounded W2           (64 MB)
__device__ float g_act[(size_t)E_ * T_ * F_];     // compacted fc1 out         (128 MB)
__device__ float g_y  [(size_t)E_ * T_ * H_];     // compacted fc2 out         (32 MB)
__device__ int   g_idx[E_ * T_];                  // per-expert gathered token ids
__device__ int   g_rowmap[T_ * E_];               // token -> g_y row (or -1)
__device__ int   g_cnt[E_];

__device__ __forceinline__ uint32_t s2u(const void* p) {
    uint32_t a;
    asm("{ .reg .u64 t; cvta.to.shared.u64 t, %1; cvt.u32.u64 %0, t; }" : "=r"(a) : "l"(p));
    return a;
}
__device__ __forceinline__ float to_tf32(float x) {
    unsigned r; asm("cvt.rna.tf32.f32 %0, %1;" : "=r"(r) : "f"(x));
    return __uint_as_float(r);
}
__device__ __forceinline__ float gelu_exact(float x) {
    return 0.5f * x * (1.0f + erff(x * 0.70710678118654752f));
}
__device__ __forceinline__ void cpa16(uint32_t d, const void* s) {
    asm volatile("cp.async.cg.shared.global [%0], [%1], 16;" :: "r"(d), "l"(s));
}
__device__ __forceinline__ void mma8(float* c, const unsigned* a, const unsigned* b) {
    asm volatile(
        "mma.sync.aligned.m16n8k8.row.col.f32.tf32.tf32.f32 "
        "{%0,%1,%2,%3}, {%4,%5,%6,%7}, {%8,%9}, {%0,%1,%2,%3};"
        : "+f"(c[0]), "+f"(c[1]), "+f"(c[2]), "+f"(c[3])
        : "r"(a[0]), "r"(a[1]), "r"(a[2]), "r"(a[3]), "r"(b[0]), "r"(b[1]));
}

// ---------------------------------------------------------------------------
// Core multistage GEMM: C[128,256] += A[128, kTiles*32] @ B[kTiles*32, 256]
// A rows optionally gathered through sidx (smem). Operands pre-rounded to tf32.
// ---------------------------------------------------------------------------
template <bool GATHER>
__device__ __forceinline__ void gemm_main(
    const float* __restrict__ Abase, int lda,
    const float* __restrict__ Bg, int ldb,
    int kTiles, const int* __restrict__ sidx,
    float c[4][8][4])
{
    extern __shared__ char smem[];
    const uint32_t sb = s2u(smem);
    const int tid = threadIdx.x;

    auto fill = [&](int kt, int stage) {
        uint32_t as = sb + HDR + stage * STAGE_BYTES;
        uint32_t bs = as + A_BYTES;
#pragma unroll
        for (int i = 0; i < 4; i++) {                 // A: 128 rows x 128B
            int idx = i * 256 + tid;
            int row = idx >> 3, seg = idx & 7;
            const float* src = GATHER
                ? Abase + (size_t)sidx[row] * lda + kt * BK + seg * 4
                : Abase + (size_t)row * lda + kt * BK + seg * 4;
            cpa16(as + (uint32_t)(row * ASTR + seg * 4) * 4, src);
        }
#pragma unroll
        for (int i = 0; i < 8; i++) {                 // B: 32 rows x 1024B
            int idx = i * 256 + tid;
            int k = idx >> 6, seg = idx & 63;
            cpa16(bs + (uint32_t)(k * BSTR + seg * 4) * 4,
                  Bg + (size_t)(kt * BK + k) * ldb + seg * 4);
        }
        asm volatile("cp.async.commit_group;" ::: "memory");
    };

#pragma unroll
    for (int s = 0; s < STAGES - 1; s++) fill(s, s);

    const int lane = tid & 31;
    const int q = lane >> 2, r = lane & 3;
    const int wm = ((tid >> 5) >> 2) * 64;            // 2 warps in M
    const int wn = ((tid >> 5) & 3) * 64;             // 4 warps in N

    for (int kt = 0; kt < kTiles; kt++) {
        asm volatile("cp.async.wait_group %0;" :: "n"(STAGES - 2) : "memory");
        __syncthreads();                              // tile kt ready; stage (kt-1)%S free
        int f = kt + STAGES - 1;
        if (f < kTiles) fill(f, f % STAGES);
        else asm volatile("cp.async.commit_group;" ::: "memory");

        const float* Ac = (const float*)(smem + HDR + (kt % STAGES) * STAGE_BYTES);
        const float* Bc = (const float*)((const char*)Ac + A_BYTES);
#pragma unroll
        for (int ks = 0; ks < 4; ks++) {
            unsigned af[4][4], bf[8][2];
            const int acol = ks * 8 + r;
#pragma unroll
            for (int mi = 0; mi < 4; mi++) {
                int row = wm + q + mi * 16;
                af[mi][0] = __float_as_uint(Ac[row * ASTR + acol]);
                af[mi][1] = __float_as_uint(Ac[(row + 8) * ASTR + acol]);
                af[mi][2] = __float_as_uint(Ac[row * ASTR + acol + 4]);
                af[mi][3] = __float_as_uint(Ac[(row + 8) * ASTR + acol + 4]);
            }
            const int brow = ks * 8 + r;
#pragma unroll
            for (int ni = 0; ni < 8; ni++) {
                int cc = wn + ni * 8 + q;
                bf[ni][0] = __float_as_uint(Bc[brow * BSTR + cc]);
                bf[ni][1] = __float_as_uint(Bc[(brow + 4) * BSTR + cc]);
            }
#pragma unroll
            for (int mi = 0; mi < 4; mi++)
#pragma unroll
                for (int ni = 0; ni < 8; ni++)
                    mma8(c[mi][ni], af[mi], bf[ni]);
        }
    }
}

// fc1: for expert e, rows = gathered tokens; out = tf32(p * gelu(x @ W1_e)), compacted
__global__ void __launch_bounds__(256, 1) fc1_kernel(const float* __restrict__ probs)
{
    const int e = blockIdx.z;
    const int cnt = g_cnt[e];
    const int m_base = blockIdx.y * BM;
    if (m_base >= cnt) return;
    const int n_base = blockIdx.x * BN;

    extern __shared__ char smem[];
    int* sidx = (int*)smem;
    if (threadIdx.x < BM) sidx[threadIdx.x] = g_idx[e * T_ + m_base + threadIdx.x];
    __syncthreads();

    float c[4][8][4];
#pragma unroll
    for (int i = 0; i < 4; i++)
#pragma unroll
        for (int j = 0; j < 8; j++)
#pragma unroll
            for (int k = 0; k < 4; k++) c[i][j][k] = 0.f;

    gemm_main<true>(g_x, H_, g_w1r + (size_t)e * H_ * F_ + n_base, F_,
                    H_ / BK, sidx, c);

    const int lane = threadIdx.x & 31;
    const int q = lane >> 2, r = lane & 3;
    const int wm = ((threadIdx.x >> 5) >> 2) * 64;
    const int wn = ((threadIdx.x >> 5) & 3) * 64;
#pragma unroll
    for (int mi = 0; mi < 4; mi++) {
        int row0 = wm + q + mi * 16, row1 = row0 + 8;
        int s0 = m_base + row0, s1 = m_base + row1;
        bool v0 = s0 < cnt, v1 = s1 < cnt;
        float p0 = v0 ? probs[(size_t)sidx[row0] * E_ + e] : 0.f;
        float p1 = v1 ? probs[(size_t)sidx[row1] * E_ + e] : 0.f;
#pragma unroll
        for (int ni = 0; ni < 8; ni++) {
            int col = n_base + wn + ni * 8 + r * 2;
            if (v0) {
                float2 o;
                o.x = to_tf32(gelu_exact(c[mi][ni][0]) * p0);
                o.y = to_tf32(gelu_exact(c[mi][ni][1]) * p0);
                *reinterpret_cast<float2*>(&g_act[((size_t)(e * T_ + s0)) * F_ + col]) = o;
            }
            if (v1) {
                float2 o;
                o.x = to_tf32(gelu_exact(c[mi][ni][2]) * p1);
                o.y = to_tf32(gelu_exact(c[mi][ni][3]) * p1);
                *reinterpret_cast<float2*>(&g_act[((size_t)(e * T_ + s1)) * F_ + col]) = o;
            }
        }
    }
}

// fc2: y = act_e @ W2_e, compacted rows (scatter deferred to combine)
__global__ void __launch_bounds__(256, 1) fc2_kernel()
{
    const int e = blockIdx.z;
    const int cnt = g_cnt[e];
    const int m_base = blockIdx.y * BM;
    if (m_base >= cnt) return;
    const int n_base = blockIdx.x * BN;

    float c[4][8][4];
#pragma unroll
    for (int i = 0; i < 4; i++)
#pragma unroll
        for (int j = 0; j < 8; j++)
#pragma unroll
            for (int k = 0; k < 4; k++) c[i][j][k] = 0.f;

    gemm_main<false>(g_act + (size_t)(e * T_ + m_base) * F_, F_,
                     g_w2r + (size_t)e * F_ * H_ + n_base, H_,
                     F_ / BK, nullptr, c);

    const int lane = threadIdx.x & 31;
    const int q = lane >> 2, r = lane & 3;
    const int wm = ((threadIdx.x >> 5) >> 2) * 64;
    const int wn = ((threadIdx.x >> 5) & 3) * 64;
#pragma unroll
    for (int mi = 0; mi < 4; mi++) {
        int row0 = wm + q + mi * 16, row1 = row0 + 8;
        int s0 = m_base + row0, s1 = m_base + row1;
#pragma unroll
        for (int ni = 0; ni < 8; ni++) {
            int col = n_base + wn + ni * 8 + r * 2;
            if (s0 < cnt) {
                float2 o = make_float2(c[mi][ni][0], c[mi][ni][1]);
                *reinterpret_cast<float2*>(&g_y[((size_t)(e * T_ + s0)) * H_ + col]) = o;
            }
            if (s1 < cnt) {
                float2 o = make_float2(c[mi][ni][2], c[mi][ni][3]);
                *reinterpret_cast<float2*>(&g_y[((size_t)(e * T_ + s1)) * H_ + col]) = o;
            }
        }
    }
}

// Deterministic per-expert ordered compaction (1 block / expert)
__global__ void __launch_bounds__(512) compact_kernel(const float* __restrict__ probs)
{
    const int e = blockIdx.x;
    const int tid = threadIdx.x;               // 512 threads, 4 tokens each
    __shared__ int ssum[512];
    __shared__ int scnt;
    const int t0 = tid * 4;
    int f[4], loc = 0;
#pragma unroll
    for (int j = 0; j < 4; j++) {
        f[j] = (probs[(size_t)(t0 + j) * E_ + e] != 0.f) ? 1 : 0;
        loc += f[j];
    }
    ssum[tid] = loc;
    __syncthreads();
    for (int off = 1; off < 512; off <<= 1) {   // inclusive Hillis-Steele scan
        int v = ssum[tid];
        int u = (tid >= off) ? ssum[tid - off] : 0;
        __syncthreads();
        ssum[tid] = v + u;
        __syncthreads();
    }
    int pos = ssum[tid] - loc;                 // exclusive base, token-ordered
    if (tid == 511) scnt = ssum[511];
    __syncthreads();
    const int cnt = scnt;
#pragma unroll
    for (int j = 0; j < 4; j++) {
        int t = t0 + j;
        if (f[j]) {
            g_idx[e * T_ + pos] = t;
            g_rowmap[t * E_ + e] = e * T_ + pos;
            pos++;
        } else {
            g_rowmap[t * E_ + e] = -1;
        }
    }
    if (tid == 0) g_cnt[e] = cnt;
    for (int i = tid; i < T_; i += 512)
        if (i >= cnt) g_idx[e * T_ + i] = 0;   // safe gather target for padded rows
}

// out[t] = resid[t] + sum over routed experts of y[row]
__global__ void __launch_bounds__(256) combine_kernel(
    const float* __restrict__ resid, float* __restrict__ out)
{
    const int i = blockIdx.x * 256 + threadIdx.x;    // float4 index over T*H/4
    const int t = i >> 8;                            // H/4 = 256
    const int co = (i & 255) * 4;
    int4 rm = *reinterpret_cast<const int4*>(&g_rowmap[t * E_]);
    float4 v = reinterpret_cast<const float4*>(resid)[i];
    if (rm.x >= 0) { float4 a = *reinterpret_cast<const float4*>(&g_y[(size_t)rm.x * H_ + co]);
                     v.x += a.x; v.y += a.y; v.z += a.z; v.w += a.w; }
    if (rm.y >= 0) { float4 a = *reinterpret_cast<const float4*>(&g_y[(size_t)rm.y * H_ + co]);
                     v.x += a.x; v.y += a.y; v.z += a.z; v.w += a.w; }
    if (rm.z >= 0) { float4 a = *reinterpret_cast<const float4*>(&g_y[(size_t)rm.z * H_ + co]);
                     v.x += a.x; v.y += a.y; v.z += a.z; v.w += a.w; }
    if (rm.w >= 0) { float4 a = *reinterpret_cast<const float4*>(&g_y[(size_t)rm.w * H_ + co]);
                     v.x += a.x; v.y += a.y; v.z += a.z; v.w += a.w; }
    reinterpret_cast<float4*>(out)[i] = v;
}

// tf32-round copy (float4 granularity)
__global__ void __launch_bounds__(256) round_copy_kernel(
    const float* __restrict__ in, float* __restrict__ dst)
{
    size_t i = (size_t)blockIdx.x * 256 + threadIdx.x;
    float4 v = reinterpret_cast<const float4*>(in)[i];
    v.x = to_tf32(v.x); v.y = to_tf32(v.y); v.z = to_tf32(v.z); v.w = to_tf32(v.w);
    reinterpret_cast<float4*>(dst)[i] = v;
}

extern "C" void kernel_launch(void* const* d_in, const int* in_sizes, int n_in,
                              void* d_out, int out_size) {
    (void)in_sizes; (void)n_in; (void)out_size;
    const float* x     = (const float*)d_in[0];   // [T, H]
    const float* resid = (const float*)d_in[1];   // [T, H]
    const float* probs = (const float*)d_in[2];   // [T, E] masked+renormalized
    // d_in[3] routing_map: redundant (probs is exactly 0 off the top-k)
    const float* w1    = (const float*)d_in[4];   // [E, H, F]  (K-major for fc1)
    const float* w2    = (const float*)d_in[5];   // [E, F, H]  (K-major for fc2)
    float* out = (float*)d_out;

    cudaFuncSetAttribute(fc1_kernel, cudaFuncAttributeMaxDynamicSharedMemorySize, SMEM_BYTES);
    cudaFuncSetAttribute(fc2_kernel, cudaFuncAttributeMaxDynamicSharedMemorySize, SMEM_BYTES);

    float* gx;  cudaGetSymbolAddress((void**)&gx,  g_x);
    float* gw1; cudaGetSymbolAddress((void**)&gw1, g_w1r);
    float* gw2; cudaGetSymbolAddress((void**)&gw2, g_w2r);

    round_copy_kernel<<<T_ * H_ / 4 / 256, 256>>>(x, gx);                    // 8 MB
    round_copy_kernel<<<E_ * H_ * F_ / 4 / 256, 256>>>(w1, gw1);             // 64 MB
    round_copy_kernel<<<E_ * F_ * H_ / 4 / 256, 256>>>(w2, gw2);             // 64 MB
    compact_kernel<<<E_, 512>>>(probs);

    fc1_kernel<<<dim3(F_ / BN, T_ / BM, E_), 256, SMEM_BYTES>>>(probs);      // 16x16x4
    fc2_kernel<<<dim3(H_ / BN, T_ / BM, E_), 256, SMEM_BYTES>>>();           // 4x16x4
    combine_kernel<<<T_ * H_ / 4 / 256, 256>>>(resid, out);
}